// round 6
// baseline (speedup 1.0000x reference)
#include <cuda_runtime.h>

// B3-spline UWT (a trous), J=3. x:(16,1024,1024)f32 -> (16,4,1024,1024)f32.
// Per level: horizontal 5-tap via warp shuffles (1 aligned LDG.128/lane/row),
// h-rows staged in smem; vertical 5-tap as a sliding window over stride-DIL
// row chains (2 LDS/row); prev kept in registers (no re-load).

#define HH 1024
#define WW 1024
#define BB 16
#define HW (HH * WW)

__device__ float g_buf0[BB * HW];
__device__ float g_buf1[BB * HW];

__device__ __forceinline__ int refl(int i, int L) {
    if (i < 0) i = -i;
    if (i >= L) i = 2 * L - 2 - i;
    return i;
}

__device__ __forceinline__ float4 shfl_up4(float4 v, int d) {
    float4 r;
    r.x = __shfl_up_sync(0xFFFFFFFFu, v.x, d);
    r.y = __shfl_up_sync(0xFFFFFFFFu, v.y, d);
    r.z = __shfl_up_sync(0xFFFFFFFFu, v.z, d);
    r.w = __shfl_up_sync(0xFFFFFFFFu, v.w, d);
    return r;
}
__device__ __forceinline__ float4 shfl_dn4(float4 v, int d) {
    float4 r;
    r.x = __shfl_down_sync(0xFFFFFFFFu, v.x, d);
    r.y = __shfl_down_sync(0xFFFFFFFFu, v.y, d);
    r.z = __shfl_down_sync(0xFFFFFFFFu, v.z, d);
    r.w = __shfl_down_sync(0xFFFFFFFFu, v.w, d);
    return r;
}

__device__ __forceinline__ float4 ldrefl4(const float* row, int g0) {
    if (g0 >= 0 && g0 + 3 < WW) return *(const float4*)(row + g0);
    float4 v;
    v.x = row[refl(g0 + 0, WW)];
    v.y = row[refl(g0 + 1, WW)];
    v.z = row[refl(g0 + 2, WW)];
    v.w = row[refl(g0 + 3, WW)];
    return v;
}

template <int DIL>
__global__ __launch_bounds__(256) void uwt_level(
    const float* __restrict__ in,     // (B,H,W) bstride HW
    float* __restrict__ detail,       // plane base, bstride 4*HW
    float* __restrict__ smooth,       // scratch (bstride HW) or c_J (4*HW)
    int sm_bs)
{
    constexpr int TX = 128, TY = 32;
    constexpr int SY  = TY + 4 * DIL;            // 36 / 40 / 48
    constexpr int NB  = (DIL == 4) ? 2 : 1;      // shuffle neighbors per side
    constexpr int CB  = 4 * NB;                  // center offset in window t[]
    constexpr int SMP = TX + 4;

    __shared__ float s_h[SY][SMP];

    const int b    = blockIdx.z;
    const int ty0  = blockIdx.y * TY;
    const int tx0  = blockIdx.x * TX;
    const int tid  = threadIdx.x;
    const int w    = tid >> 5;
    const int lane = tid & 31;

    const float* base = in + b * HW;
    const int c0  = 4 * lane;
    const int gx0 = tx0 + c0;

    const float w0 = 0.0625f, w1 = 0.25f, w2 = 0.375f;

    // chain start for this warp (phase B rows rr = r0 + i*DIL, i=0..3)
    const int r0 = (w / DIL) * (4 * DIL) + (w % DIL);

    float4 pv[4];   // prev (original input) for this warp's output rows

    // ---- Phase A: horizontal conv of one image row -> s_h[r] --------------
    auto process_row = [&](int r) -> float4 {
        const int gy = refl(ty0 - 2 * DIL + r, HH);
        const float* row = base + gy * WW;
        float4 v = *(const float4*)(row + gx0);   // gx0 always in-bounds

        float t[4 * (2 * NB + 1)];
        *(float4*)&t[CB] = v;
        #pragma unroll
        for (int d = 1; d <= NB; d++) {
            float4 a = shfl_up4(v, d);
            if (lane < d) a = ldrefl4(row, gx0 - 4 * d);
            *(float4*)&t[4 * (NB - d)] = a;
            float4 p = shfl_dn4(v, d);
            if (lane >= 32 - d) p = ldrefl4(row, gx0 + 4 * d);
            *(float4*)&t[4 * (NB + d)] = p;
        }

        float4 h;
        h.x = w0 * (t[CB + 0 - 2*DIL] + t[CB + 0 + 2*DIL])
            + w1 * (t[CB + 0 -   DIL] + t[CB + 0 +   DIL]) + w2 * t[CB + 0];
        h.y = w0 * (t[CB + 1 - 2*DIL] + t[CB + 1 + 2*DIL])
            + w1 * (t[CB + 1 -   DIL] + t[CB + 1 +   DIL]) + w2 * t[CB + 1];
        h.z = w0 * (t[CB + 2 - 2*DIL] + t[CB + 2 + 2*DIL])
            + w1 * (t[CB + 2 -   DIL] + t[CB + 2 +   DIL]) + w2 * t[CB + 2];
        h.w = w0 * (t[CB + 3 - 2*DIL] + t[CB + 3 + 2*DIL])
            + w1 * (t[CB + 3 -   DIL] + t[CB + 3 +   DIL]) + w2 * t[CB + 3];
        *(float4*)&s_h[r][c0] = h;
        return v;
    };

    // prev rows: s_h index r = rr + 2*DIL for this warp's output rows
    #pragma unroll
    for (int i = 0; i < 4; i++)
        pv[i] = process_row(r0 + 2 * DIL + i * DIL);

    // halo rows: indices [0,2*DIL) and [2*DIL+TY, SY), distributed by warp
    #pragma unroll
    for (int j = w; j < 4 * DIL; j += 8) {
        const int r = (j < 2 * DIL) ? j : j + TY;
        process_row(r);
    }
    __syncthreads();

    // ---- Phase B: vertical conv, sliding 5-row window over the chain ------
    float4 win[5];
    #pragma unroll
    for (int k = 0; k < 5; k++)
        win[k] = *(const float4*)&s_h[r0 + k * DIL][c0];

    #pragma unroll
    for (int i = 0; i < 4; i++) {
        const int rr = r0 + i * DIL;

        float4 sm;
        sm.x = w0 * (win[0].x + win[4].x) + w1 * (win[1].x + win[3].x) + w2 * win[2].x;
        sm.y = w0 * (win[0].y + win[4].y) + w1 * (win[1].y + win[3].y) + w2 * win[2].y;
        sm.z = w0 * (win[0].z + win[4].z) + w1 * (win[1].z + win[3].z) + w2 * win[2].z;
        sm.w = w0 * (win[0].w + win[4].w) + w1 * (win[1].w + win[3].w) + w2 * win[2].w;

        float4 dt = make_float4(pv[i].x - sm.x, pv[i].y - sm.y,
                                pv[i].z - sm.z, pv[i].w - sm.w);

        const int off = (ty0 + rr) * WW + gx0;
        *(float4*)(detail + b * 4 * HW + off) = dt;
        *(float4*)(smooth + b * sm_bs  + off) = sm;

        if (i < 3) {
            win[0] = win[1]; win[1] = win[2]; win[2] = win[3]; win[3] = win[4];
            win[4] = *(const float4*)&s_h[r0 + (i + 5) * DIL][c0];
        }
    }
}

extern "C" void kernel_launch(void* const* d_in, const int* in_sizes, int n_in,
                              void* d_out, int out_size)
{
    (void)in_sizes; (void)n_in; (void)out_size;
    const float* x = (const float*)d_in[0];
    float* out = (float*)d_out;

    float *b0, *b1;
    cudaGetSymbolAddress((void**)&b0, g_buf0);
    cudaGetSymbolAddress((void**)&b1, g_buf1);

    dim3 grid(WW / 128, HH / 32, BB);
    dim3 block(256);

    uwt_level<1><<<grid, block>>>(x,  out + 0 * HW, b0, HW);
    uwt_level<2><<<grid, block>>>(b0, out + 1 * HW, b1, HW);
    uwt_level<4><<<grid, block>>>(b1, out + 2 * HW, out + 3 * HW, 4 * HW);
}

// round 7
// speedup vs baseline: 1.2320x; 1.2320x over previous
#include <cuda_runtime.h>

// B3-spline UWT (a trous), J=3. x:(16,1024,1024)f32 -> (16,4,1024,1024)f32.
// Per level: horizontal 5-tap via warp shuffles (1 aligned LDG.128/lane/row),
// h-rows staged in smem; vertical 5-tap as a sliding window over stride-DIL
// row chains (2 LDS/row); prev re-read from gmem (L1 hit) to keep regs low.

#define HH 1024
#define WW 1024
#define BB 16
#define HW (HH * WW)

__device__ float g_buf0[BB * HW];
__device__ float g_buf1[BB * HW];

__device__ __forceinline__ int refl(int i, int L) {
    if (i < 0) i = -i;
    if (i >= L) i = 2 * L - 2 - i;
    return i;
}

__device__ __forceinline__ float4 shfl_up4(float4 v, int d) {
    float4 r;
    r.x = __shfl_up_sync(0xFFFFFFFFu, v.x, d);
    r.y = __shfl_up_sync(0xFFFFFFFFu, v.y, d);
    r.z = __shfl_up_sync(0xFFFFFFFFu, v.z, d);
    r.w = __shfl_up_sync(0xFFFFFFFFu, v.w, d);
    return r;
}
__device__ __forceinline__ float4 shfl_dn4(float4 v, int d) {
    float4 r;
    r.x = __shfl_down_sync(0xFFFFFFFFu, v.x, d);
    r.y = __shfl_down_sync(0xFFFFFFFFu, v.y, d);
    r.z = __shfl_down_sync(0xFFFFFFFFu, v.z, d);
    r.w = __shfl_down_sync(0xFFFFFFFFu, v.w, d);
    return r;
}

__device__ __forceinline__ float4 ldrefl4(const float* row, int g0) {
    if (g0 >= 0 && g0 + 3 < WW) return *(const float4*)(row + g0);
    float4 v;
    v.x = row[refl(g0 + 0, WW)];
    v.y = row[refl(g0 + 1, WW)];
    v.z = row[refl(g0 + 2, WW)];
    v.w = row[refl(g0 + 3, WW)];
    return v;
}

template <int DIL>
__global__ __launch_bounds__(256, 6) void uwt_level(
    const float* __restrict__ in,     // (B,H,W) bstride HW
    float* __restrict__ detail,       // plane base, bstride 4*HW
    float* __restrict__ smooth,       // scratch (bstride HW) or c_J (4*HW)
    int sm_bs)
{
    constexpr int TX = 128, TY = 32;
    constexpr int SY  = TY + 4 * DIL;            // 36 / 40 / 48
    constexpr int NB  = (DIL == 4) ? 2 : 1;      // shuffle neighbors per side
    constexpr int CB  = 4 * NB;                  // center offset in window t[]
    constexpr int SMP = TX + 4;

    __shared__ float s_h[SY][SMP];

    const int b    = blockIdx.z;
    const int ty0  = blockIdx.y * TY;
    const int tx0  = blockIdx.x * TX;
    const int tid  = threadIdx.x;
    const int w    = tid >> 5;
    const int lane = tid & 31;

    const float* base = in + b * HW;
    const int c0  = 4 * lane;
    const int gx0 = tx0 + c0;

    const float w0 = 0.0625f, w1 = 0.25f, w2 = 0.375f;

    // chain start for this warp (phase B rows rr = r0 + i*DIL, i=0..3)
    const int r0 = (w / DIL) * (4 * DIL) + (w % DIL);

    // ---- Phase A: horizontal conv of one image row -> s_h[r] --------------
    auto process_row = [&](int r, float4 v) {
        const int gy = refl(ty0 - 2 * DIL + r, HH);
        const float* row = base + gy * WW;

        float t[4 * (2 * NB + 1)];
        *(float4*)&t[CB] = v;
        #pragma unroll
        for (int d = 1; d <= NB; d++) {
            float4 a = shfl_up4(v, d);
            if (lane < d) a = ldrefl4(row, gx0 - 4 * d);
            *(float4*)&t[4 * (NB - d)] = a;
            float4 p = shfl_dn4(v, d);
            if (lane >= 32 - d) p = ldrefl4(row, gx0 + 4 * d);
            *(float4*)&t[4 * (NB + d)] = p;
        }

        float4 h;
        h.x = w0 * (t[CB + 0 - 2*DIL] + t[CB + 0 + 2*DIL])
            + w1 * (t[CB + 0 -   DIL] + t[CB + 0 +   DIL]) + w2 * t[CB + 0];
        h.y = w0 * (t[CB + 1 - 2*DIL] + t[CB + 1 + 2*DIL])
            + w1 * (t[CB + 1 -   DIL] + t[CB + 1 +   DIL]) + w2 * t[CB + 1];
        h.z = w0 * (t[CB + 2 - 2*DIL] + t[CB + 2 + 2*DIL])
            + w1 * (t[CB + 2 -   DIL] + t[CB + 2 +   DIL]) + w2 * t[CB + 2];
        h.w = w0 * (t[CB + 3 - 2*DIL] + t[CB + 3 + 2*DIL])
            + w1 * (t[CB + 3 -   DIL] + t[CB + 3 +   DIL]) + w2 * t[CB + 3];
        *(float4*)&s_h[r][c0] = h;
    };

    // chain rows: issue all 4 independent LDGs up front (MLP), then process
    {
        float4 v[4];
        #pragma unroll
        for (int i = 0; i < 4; i++) {
            const int gy = refl(ty0 + r0 + i * DIL, HH);   // = ty0-2D + (r0+2D+iD)
            v[i] = *(const float4*)(base + gy * WW + gx0);
        }
        #pragma unroll
        for (int i = 0; i < 4; i++)
            process_row(r0 + 2 * DIL + i * DIL, v[i]);
    }

    // halo rows: indices [0,2*DIL) and [2*DIL+TY, SY), distributed by warp
    #pragma unroll
    for (int j = w; j < 4 * DIL; j += 8) {
        const int r  = (j < 2 * DIL) ? j : j + TY;
        const int gy = refl(ty0 - 2 * DIL + r, HH);
        float4 v = *(const float4*)(base + gy * WW + gx0);
        process_row(r, v);
    }
    __syncthreads();

    // ---- Phase B: vertical conv, sliding 5-row window over the chain ------
    float4 win[5];
    #pragma unroll
    for (int k = 0; k < 5; k++)
        win[k] = *(const float4*)&s_h[r0 + k * DIL][c0];

    #pragma unroll
    for (int i = 0; i < 4; i++) {
        const int rr  = r0 + i * DIL;
        const int off = (ty0 + rr) * WW + gx0;

        float4 prev = __ldg((const float4*)(base + off));   // L1 hit (phase A line)

        float4 sm;
        sm.x = w0 * (win[0].x + win[4].x) + w1 * (win[1].x + win[3].x) + w2 * win[2].x;
        sm.y = w0 * (win[0].y + win[4].y) + w1 * (win[1].y + win[3].y) + w2 * win[2].y;
        sm.z = w0 * (win[0].z + win[4].z) + w1 * (win[1].z + win[3].z) + w2 * win[2].z;
        sm.w = w0 * (win[0].w + win[4].w) + w1 * (win[1].w + win[3].w) + w2 * win[2].w;

        float4 dt = make_float4(prev.x - sm.x, prev.y - sm.y,
                                prev.z - sm.z, prev.w - sm.w);

        *(float4*)(detail + b * 4 * HW + off) = dt;
        *(float4*)(smooth + b * sm_bs  + off) = sm;

        if (i < 3) {
            win[0] = win[1]; win[1] = win[2]; win[2] = win[3]; win[3] = win[4];
            win[4] = *(const float4*)&s_h[r0 + (i + 5) * DIL][c0];
        }
    }
}

extern "C" void kernel_launch(void* const* d_in, const int* in_sizes, int n_in,
                              void* d_out, int out_size)
{
    (void)in_sizes; (void)n_in; (void)out_size;
    const float* x = (const float*)d_in[0];
    float* out = (float*)d_out;

    float *b0, *b1;
    cudaGetSymbolAddress((void**)&b0, g_buf0);
    cudaGetSymbolAddress((void**)&b1, g_buf1);

    dim3 grid(WW / 128, HH / 32, BB);
    dim3 block(256);

    uwt_level<1><<<grid, block>>>(x,  out + 0 * HW, b0, HW);
    uwt_level<2><<<grid, block>>>(b0, out + 1 * HW, b1, HW);
    uwt_level<4><<<grid, block>>>(b1, out + 2 * HW, out + 3 * HW, 4 * HW);
}